// round 14
// baseline (speedup 1.0000x reference)
#include <cuda_runtime.h>

#define NB 262144
#define BLOCK 128

typedef unsigned long long u64;

struct CW {
    ulonglong2 W1[32][4];   // [k][j2]: 4 feature-pairs per 16B
    ulonglong2 W2[32][4];   // [k][j2]: output pairs, native W2 row-major
    u64 wqb[32];            // (W1[0][k], b1[k]) — pairs with input (q, 1)
    u64 W3[8];              // native pairs
    u64 b2[8];              // native pairs
    float b3;
    float qp[7];            // q_params (only 1..6 used)
};

__constant__ CW cw;
__device__ CW d_stage;

__device__ __forceinline__ u64 pack2(float lo, float hi) {
    u64 r; asm("mov.b64 %0, {%1,%2};" : "=l"(r) : "f"(lo), "f"(hi)); return r;
}
__device__ __forceinline__ void unpack2(u64 v, float& lo, float& hi) {
    asm("mov.b64 {%0,%1}, %2;" : "=f"(lo), "=f"(hi) : "l"(v));
}
__device__ __forceinline__ u64 fma2(u64 a, u64 b, u64 c) {
    u64 r; asm("fma.rn.f32x2 %0, %1, %2, %3;" : "=l"(r) : "l"(a), "l"(b), "l"(c)); return r;
}
__device__ __forceinline__ u64 mul2(u64 a, u64 b) {
    u64 r; asm("mul.rn.f32x2 %0, %1, %2;" : "=l"(r) : "l"(a), "l"(b)); return r;
}
__device__ __forceinline__ u64 add2(u64 a, u64 b) {
    u64 r; asm("add.rn.f32x2 %0, %1, %2;" : "=l"(r) : "l"(a), "l"(b)); return r;
}
__device__ __forceinline__ u64 relu2(u64 x) {
    float lo, hi; unpack2(x, lo, hi);
    lo = fmaxf(lo, 0.0f); hi = fmaxf(hi, 0.0f);
    return pack2(lo, hi);
}

__global__ void prep_kernel(const float* __restrict__ W1, const float* __restrict__ b1,
                            const float* __restrict__ W2, const float* __restrict__ b2,
                            const float* __restrict__ W3, const float* __restrict__ b3,
                            const float* __restrict__ qp)
{
    const int tid = threadIdx.x;
    for (int i = tid; i < 32 * 4; i += blockDim.x) {
        int k = i / 4, j2 = i % 4;
        ulonglong2 a;
        a.x = pack2(W1[(1 + 4 * j2) * 32 + k], W1[(2 + 4 * j2) * 32 + k]);
        a.y = pack2(W1[(3 + 4 * j2) * 32 + k], W1[(4 + 4 * j2) * 32 + k]);
        d_stage.W1[k][j2] = a;
        ulonglong2 b;
        b.x = ((const u64*)W2)[k * 8 + 2 * j2];
        b.y = ((const u64*)W2)[k * 8 + 2 * j2 + 1];
        d_stage.W2[k][j2] = b;
    }
    if (tid < 32) d_stage.wqb[tid] = pack2(W1[tid], b1[tid]);
    if (tid < 8) {
        d_stage.W3[tid] = ((const u64*)W3)[tid];
        d_stage.b2[tid] = ((const u64*)b2)[tid];
    }
    if (tid < 7) d_stage.qp[tid] = qp[tid];
    if (tid == 0) d_stage.b3 = b3[0];
}

__global__ __launch_bounds__(BLOCK, 8)   // 64-reg cap -> 32 warps/SM
void hybridq_kernel(const float* __restrict__ xq, const float* __restrict__ xc,
                    float* __restrict__ out)
{
    const int t = blockIdx.x * BLOCK + threadIdx.x;

    // ---- Quantum feature: <Z0> = prod_{i=1..6} cos(x_q[i] + qp[i]) ----
    // (CNOT-ring GF(2): qubit-0 output = parity(b1..b6); per-qubit factor
    //  cos^2(h)-sin^2(h) = cos(2h) = cos(x+w); qubit 0's own angle cancels.)
    float q0 = 1.0f;
#pragma unroll
    for (int i = 1; i < 7; i++)
        q0 *= __cosf(__ldg(xq + (size_t)t * 7 + i) + cw.qp[i]);

    // ---- Inputs: 8 native xc pairs + (q, 1) pair (bias folded as feature) ----
    u64 in[9];
    in[8] = pack2(q0, 1.0f);
    {
        const ulonglong2* c0 = (const ulonglong2*)(xc + (size_t)t * 16);
#pragma unroll
        for (int p = 0; p < 4; p++) {
            ulonglong2 a = c0[p];
            in[2 * p] = a.x;
            in[2 * p + 1] = a.y;
        }
    }

    // ---- h2 accumulators: 8 output-pairs, init with b2 (const) ----
    u64 h2[8];
#pragma unroll
    for (int j = 0; j < 8; j++)
        h2[j] = cw.b2[j];

    // ---- Fused layers 1+2; weights ride the const/uniform port ----
#pragma unroll 2
    for (int k = 0; k < 32; k++) {
        ulonglong2 w01 = cw.W1[k][0];
        ulonglong2 w23 = cw.W1[k][1];
        ulonglong2 w45 = cw.W1[k][2];
        ulonglong2 w67 = cw.W1[k][3];

        // Two independent chains (even/odd), merged once: depth 5.
        u64 accA = mul2(in[0], w01.x);
        u64 accB = mul2(in[1], w01.y);
        accA = fma2(in[2], w23.x, accA);
        accB = fma2(in[3], w23.y, accB);
        accA = fma2(in[4], w45.x, accA);
        accB = fma2(in[5], w45.y, accB);
        accA = fma2(in[6], w67.x, accA);
        accB = fma2(in[7], w67.y, accB);
        accA = fma2(in[8], cw.wqb[k], accA);   // q*W1q + 1*b1 folded in
        u64 acc = add2(accA, accB);
        float lo, hi;
        unpack2(acc, lo, hi);                  // free: register pair
        float s = fmaxf(lo + hi, 0.0f);
        u64 a2 = pack2(s, s);

        ulonglong2 v01 = cw.W2[k][0];
        ulonglong2 v23 = cw.W2[k][1];
        ulonglong2 v45 = cw.W2[k][2];
        ulonglong2 v67 = cw.W2[k][3];
        h2[0] = fma2(a2, v01.x, h2[0]);
        h2[1] = fma2(a2, v01.y, h2[1]);
        h2[2] = fma2(a2, v23.x, h2[2]);
        h2[3] = fma2(a2, v23.y, h2[3]);
        h2[4] = fma2(a2, v45.x, h2[4]);
        h2[5] = fma2(a2, v45.y, h2[5]);
        h2[6] = fma2(a2, v67.x, h2[6]);
        h2[7] = fma2(a2, v67.y, h2[7]);
    }

    // ---- Layer 3: relu(h2) . W3 + b3, pairwise (2 chains) then hsum ----
    u64 accA = mul2(relu2(h2[0]), cw.W3[0]);
    u64 accB = mul2(relu2(h2[1]), cw.W3[1]);
#pragma unroll
    for (int j = 2; j < 8; j += 2) {
        accA = fma2(relu2(h2[j]), cw.W3[j], accA);
        accB = fma2(relu2(h2[j + 1]), cw.W3[j + 1], accB);
    }
    u64 acc = add2(accA, accB);
    float lo, hi;
    unpack2(acc, lo, hi);
    out[t] = cw.b3 + lo + hi;
}

extern "C" void kernel_launch(void* const* d_in, const int* in_sizes, int n_in,
                              void* d_out, int out_size)
{
    const float* xq = (const float*)d_in[0];
    const float* xc = (const float*)d_in[1];
    const float* qp = (const float*)d_in[2];
    const float* W1 = (const float*)d_in[3];
    const float* b1 = (const float*)d_in[4];
    const float* W2 = (const float*)d_in[5];
    const float* b2 = (const float*)d_in[6];
    const float* W3 = (const float*)d_in[7];
    const float* b3 = (const float*)d_in[8];
    float* out = (float*)d_out;

    // 1. Pack weights into the staging struct (device).
    prep_kernel<<<1, 128>>>(W1, b1, W2, b2, W3, b3, qp);

    // 2. Staging -> constant bank (D2D async memcpy; graph-capturable node).
    void* stage_ptr = nullptr;
    cudaGetSymbolAddress(&stage_ptr, d_stage);
    cudaMemcpyToSymbolAsync(cw, stage_ptr, sizeof(CW), 0, cudaMemcpyDeviceToDevice, 0);

    // 3. Main kernel: EPT=1, high occupancy, weights on the const/uniform port.
    hybridq_kernel<<<NB / BLOCK, BLOCK>>>(xq, xc, out);
}

// round 15
// speedup vs baseline: 1.2076x; 1.2076x over previous
#include <cuda_runtime.h>

#define NB 262144
#define NTH4 (NB / 4)   // 65536 threads, 4 elements each
#define BLOCK 128

typedef unsigned long long u64;

struct CW {
    ulonglong2 W1[32][4];   // [k][j2]: 4 feature-pairs per 16B
    ulonglong2 W2[32][4];   // [k][j2]: output pairs, native W2 row-major
    u64 wqb[32];            // (W1[0][k], b1[k]) — pairs with input (q, 1)
    u64 W3[8];              // native pairs
    u64 b2[8];              // native pairs
    float b3;
    float qp[7];            // q_params (only 1..6 used)
};

__constant__ CW cw;
__device__ CW d_stage;

__device__ __forceinline__ u64 pack2(float lo, float hi) {
    u64 r; asm("mov.b64 %0, {%1,%2};" : "=l"(r) : "f"(lo), "f"(hi)); return r;
}
__device__ __forceinline__ void unpack2(u64 v, float& lo, float& hi) {
    asm("mov.b64 {%0,%1}, %2;" : "=f"(lo), "=f"(hi) : "l"(v));
}
__device__ __forceinline__ u64 fma2(u64 a, u64 b, u64 c) {
    u64 r; asm("fma.rn.f32x2 %0, %1, %2, %3;" : "=l"(r) : "l"(a), "l"(b), "l"(c)); return r;
}
__device__ __forceinline__ u64 mul2(u64 a, u64 b) {
    u64 r; asm("mul.rn.f32x2 %0, %1, %2;" : "=l"(r) : "l"(a), "l"(b)); return r;
}
__device__ __forceinline__ u64 add2(u64 a, u64 b) {
    u64 r; asm("add.rn.f32x2 %0, %1, %2;" : "=l"(r) : "l"(a), "l"(b)); return r;
}
__device__ __forceinline__ u64 relu2(u64 x) {
    float lo, hi; unpack2(x, lo, hi);
    lo = fmaxf(lo, 0.0f); hi = fmaxf(hi, 0.0f);
    return pack2(lo, hi);
}

__global__ void prep_kernel(const float* __restrict__ W1, const float* __restrict__ b1,
                            const float* __restrict__ W2, const float* __restrict__ b2,
                            const float* __restrict__ W3, const float* __restrict__ b3,
                            const float* __restrict__ qp)
{
    const int tid = threadIdx.x;
    for (int i = tid; i < 32 * 4; i += blockDim.x) {
        int k = i / 4, j2 = i % 4;
        ulonglong2 a;
        a.x = pack2(W1[(1 + 4 * j2) * 32 + k], W1[(2 + 4 * j2) * 32 + k]);
        a.y = pack2(W1[(3 + 4 * j2) * 32 + k], W1[(4 + 4 * j2) * 32 + k]);
        d_stage.W1[k][j2] = a;
        ulonglong2 b;
        b.x = ((const u64*)W2)[k * 8 + 2 * j2];
        b.y = ((const u64*)W2)[k * 8 + 2 * j2 + 1];
        d_stage.W2[k][j2] = b;
    }
    if (tid < 32) d_stage.wqb[tid] = pack2(W1[tid], b1[tid]);
    if (tid < 8) {
        d_stage.W3[tid] = ((const u64*)W3)[tid];
        d_stage.b2[tid] = ((const u64*)b2)[tid];
    }
    if (tid < 7) d_stage.qp[tid] = qp[tid];
    if (tid == 0) d_stage.b3 = b3[0];
}

__global__ __launch_bounds__(BLOCK, 3)   // 170-reg cap; EPT=4 live set ~162
void hybridq_kernel(const float* __restrict__ xq, const float* __restrict__ xc,
                    float* __restrict__ out)
{
    const int t = blockIdx.x * BLOCK + threadIdx.x;

    // ---- Quantum feature: <Z0> = prod_{i=1..6} cos(x_q[i] + qp[i]) ----
    // (CNOT-ring GF(2): qubit-0 output = parity(b1..b6); per-qubit factor
    //  cos^2(h)-sin^2(h) = cos(2h) = cos(x+w); qubit 0's own angle cancels.)
    float q[4] = {1.0f, 1.0f, 1.0f, 1.0f};
#pragma unroll
    for (int i = 1; i < 7; i++) {
        float w = cw.qp[i];
        q[0] *= __cosf(__ldg(xq + (size_t)t * 7 + i) + w);
        q[1] *= __cosf(__ldg(xq + ((size_t)t + NTH4) * 7 + i) + w);
        q[2] *= __cosf(__ldg(xq + ((size_t)t + 2 * NTH4) * 7 + i) + w);
        q[3] *= __cosf(__ldg(xq + ((size_t)t + 3 * NTH4) * 7 + i) + w);
    }

    // ---- Inputs: 8 native xc pairs + (q, 1) pair per element ----
    u64 in[4][9];
#pragma unroll
    for (int e = 0; e < 4; e++) {
        in[e][8] = pack2(q[e], 1.0f);
        const ulonglong2* c = (const ulonglong2*)(xc + ((size_t)t + e * NTH4) * 16);
#pragma unroll
        for (int p = 0; p < 4; p++) {
            ulonglong2 a = c[p];
            in[e][2 * p] = a.x;
            in[e][2 * p + 1] = a.y;
        }
    }

    // ---- h2 accumulators: 8 output-pairs per element, init with b2 ----
    u64 h2[4][8];
#pragma unroll
    for (int e = 0; e < 4; e++)
#pragma unroll
        for (int j = 0; j < 8; j++)
            h2[e][j] = cw.b2[j];

    // ---- Fused layers 1+2; weights ride the const/uniform port ----
#pragma unroll 2
    for (int k = 0; k < 32; k++) {
        ulonglong2 w01 = cw.W1[k][0];
        ulonglong2 w23 = cw.W1[k][1];
        ulonglong2 w45 = cw.W1[k][2];
        ulonglong2 w67 = cw.W1[k][3];
        u64 wqb = cw.wqb[k];

        u64 a2[4];
#pragma unroll
        for (int e = 0; e < 4; e++) {
            // Two independent chains (even/odd features), merged once.
            u64 accA = mul2(in[e][0], w01.x);
            u64 accB = mul2(in[e][1], w01.y);
            accA = fma2(in[e][2], w23.x, accA);
            accB = fma2(in[e][3], w23.y, accB);
            accA = fma2(in[e][4], w45.x, accA);
            accB = fma2(in[e][5], w45.y, accB);
            accA = fma2(in[e][6], w67.x, accA);
            accB = fma2(in[e][7], w67.y, accB);
            accA = fma2(in[e][8], wqb, accA);   // q*W1q + 1*b1 folded in
            u64 acc = add2(accA, accB);
            float lo, hi;
            unpack2(acc, lo, hi);               // free: register pair
            float s = fmaxf(lo + hi, 0.0f);
            a2[e] = pack2(s, s);
        }

        ulonglong2 v01 = cw.W2[k][0];
        ulonglong2 v23 = cw.W2[k][1];
        ulonglong2 v45 = cw.W2[k][2];
        ulonglong2 v67 = cw.W2[k][3];
#pragma unroll
        for (int e = 0; e < 4; e++) {
            h2[e][0] = fma2(a2[e], v01.x, h2[e][0]);
            h2[e][1] = fma2(a2[e], v01.y, h2[e][1]);
            h2[e][2] = fma2(a2[e], v23.x, h2[e][2]);
            h2[e][3] = fma2(a2[e], v23.y, h2[e][3]);
            h2[e][4] = fma2(a2[e], v45.x, h2[e][4]);
            h2[e][5] = fma2(a2[e], v45.y, h2[e][5]);
            h2[e][6] = fma2(a2[e], v67.x, h2[e][6]);
            h2[e][7] = fma2(a2[e], v67.y, h2[e][7]);
        }
    }

    // ---- Layer 3: relu(h2) . W3 + b3, pairwise (2 chains) then hsum ----
    const float bb = cw.b3;
#pragma unroll
    for (int e = 0; e < 4; e++) {
        u64 accA = mul2(relu2(h2[e][0]), cw.W3[0]);
        u64 accB = mul2(relu2(h2[e][1]), cw.W3[1]);
#pragma unroll
        for (int j = 2; j < 8; j += 2) {
            accA = fma2(relu2(h2[e][j]), cw.W3[j], accA);
            accB = fma2(relu2(h2[e][j + 1]), cw.W3[j + 1], accB);
        }
        u64 acc = add2(accA, accB);
        float lo, hi;
        unpack2(acc, lo, hi);
        out[t + e * NTH4] = bb + lo + hi;
    }
}

extern "C" void kernel_launch(void* const* d_in, const int* in_sizes, int n_in,
                              void* d_out, int out_size)
{
    const float* xq = (const float*)d_in[0];
    const float* xc = (const float*)d_in[1];
    const float* qp = (const float*)d_in[2];
    const float* W1 = (const float*)d_in[3];
    const float* b1 = (const float*)d_in[4];
    const float* W2 = (const float*)d_in[5];
    const float* b2 = (const float*)d_in[6];
    const float* W3 = (const float*)d_in[7];
    const float* b3 = (const float*)d_in[8];
    float* out = (float*)d_out;

    // 1. Pack weights into the staging struct (device).
    prep_kernel<<<1, 128>>>(W1, b1, W2, b2, W3, b3, qp);

    // 2. Staging -> constant bank (D2D async memcpy; graph-capturable node).
    void* stage_ptr = nullptr;
    cudaGetSymbolAddress(&stage_ptr, d_stage);
    cudaMemcpyToSymbolAsync(cw, stage_ptr, sizeof(CW), 0, cudaMemcpyDeviceToDevice, 0);

    // 3. Main kernel: EPT=4, const weights, max per-warp ILP.
    hybridq_kernel<<<NTH4 / BLOCK, BLOCK>>>(xq, xc, out);
}